// round 1
// baseline (speedup 1.0000x reference)
#include <cuda_runtime.h>
#include <math.h>

// ----------------------------------------------------------------------------
// DARTS-style supernet forward:
//   states = [s0, s1, cat(s0,s1)]
//   node i (i=0..3): s = sum_j mixed(states[j], W_l, b_l, geno_l), l = offset+j
//   mixed(x,W,b,w) = sum_k w[k] * act_k(x @ W[k] + b[k]),  5 ops
// Output = node 3 result  [4096, 1024] fp32.
//
// This round: fused fp32 SGEMM per node. Each CTA computes a 128x128 tile of
// the node output; loops over (edge, op), runs full-K reduction in registers,
// applies bias + activation + genotype weight, accumulates into a second
// register tile. No intermediates in HBM, no atomics. "cat" edge reads s0 for
// k<1024 and s1 for k>=1024 (no concat buffer).
// ----------------------------------------------------------------------------

#define BM 128
#define BN 128
#define BK 16
#define NTHREADS 256

#define BATCH 4096
#define DDIM  1024

struct EdgeDesc {
    const float* xa;    // input for k <  ksplit
    const float* xb;    // input for k >= ksplit
    const float* W;     // [5, K, 1024]
    int K;              // 1024 or 2048
    int ksplit;         // 1024 (cat edge) or == K (normal edge)
    int layer;          // global layer index l (for genotype / bias)
};

struct NodeArgs {
    EdgeDesc e[6];
    int n_edges;
};

// Scratch for node outputs 0..2 (node 3 goes to d_out). Static device arrays
// per harness rules (no cudaMalloc anywhere).
__device__ float g_node0[BATCH * DDIM];
__device__ float g_node1[BATCH * DDIM];
__device__ float g_node2[BATCH * DDIM];

__global__ __launch_bounds__(NTHREADS, 1)
void node_kernel(NodeArgs args,
                 const float* __restrict__ geno,   // [18,5]
                 const float* __restrict__ bsv,    // [18,5,1024]
                 float* __restrict__ out)          // [4096,1024]
{
    __shared__ float As[BK][BM];   // x tile, transposed: As[k][m]
    __shared__ float Bs[BK][BN];   // W tile: Bs[k][n]

    const int bm = blockIdx.y * BM;
    const int bn = blockIdx.x * BN;
    const int tid = (int)threadIdx.x;
    const int tx = tid & 15;        // 16 thread-cols
    const int ty = tid >> 4;        // 16 thread-rows
    const int tm = ty * 8;
    const int tn = tx * 8;

    float accs[8][8];               // mixed-op accumulator (final tile)
    #pragma unroll
    for (int i = 0; i < 8; i++)
        #pragma unroll
        for (int j = 0; j < 8; j++)
            accs[i][j] = 0.0f;

    for (int e = 0; e < args.n_edges; e++) {
        const EdgeDesc ed = args.e[e];
        const int ntiles = ed.K / BK;

        for (int op = 0; op < 5; op++) {            // do NOT unroll: keeps I$ small
            const float* __restrict__ Wop = ed.W + (size_t)op * ed.K * DDIM;

            float acc[8][8];                        // per-(edge,op) GEMM accumulator
            #pragma unroll
            for (int i = 0; i < 8; i++)
                #pragma unroll
                for (int j = 0; j < 8; j++)
                    acc[i][j] = 0.0f;

            for (int kt = 0; kt < ntiles; kt++) {
                const int kg = kt * BK;
                const float* xbase = ed.xa;
                int koff = kg;
                if (kg >= ed.ksplit) { xbase = ed.xb; koff = kg - ed.ksplit; }

                // ---- load A tile: 128 rows x 16 k-cols (2 float4 per thread)
                #pragma unroll
                for (int rpt = 0; rpt < 2; rpt++) {
                    const int f  = tid + rpt * NTHREADS;   // 0..511
                    const int r  = f >> 2;                 // 0..127
                    const int c4 = f & 3;                  // 0..3
                    float4 v = *(const float4*)(xbase + (size_t)(bm + r) * DDIM + koff + c4 * 4);
                    As[c4 * 4 + 0][r] = v.x;
                    As[c4 * 4 + 1][r] = v.y;
                    As[c4 * 4 + 2][r] = v.z;
                    As[c4 * 4 + 3][r] = v.w;
                }
                // ---- load B tile: 16 k-rows x 128 cols (2 float4 per thread)
                #pragma unroll
                for (int rpt = 0; rpt < 2; rpt++) {
                    const int f  = tid + rpt * NTHREADS;   // 0..511
                    const int r  = f >> 5;                 // 0..15
                    const int c4 = f & 31;                 // 0..31
                    float4 v = *(const float4*)(Wop + (size_t)(kg + r) * DDIM + bn + c4 * 4);
                    *(float4*)&Bs[r][c4 * 4] = v;
                }
                __syncthreads();

                #pragma unroll
                for (int kk = 0; kk < BK; kk++) {
                    float a[8], b[8];
                    *(float4*)&a[0] = *(const float4*)&As[kk][tm];
                    *(float4*)&a[4] = *(const float4*)&As[kk][tm + 4];
                    *(float4*)&b[0] = *(const float4*)&Bs[kk][tn];
                    *(float4*)&b[4] = *(const float4*)&Bs[kk][tn + 4];
                    #pragma unroll
                    for (int i = 0; i < 8; i++)
                        #pragma unroll
                        for (int j = 0; j < 8; j++)
                            acc[i][j] = fmaf(a[i], b[j], acc[i][j]);
                }
                __syncthreads();
            }

            // ---- epilogue: h = acc + bias; accs += w * act_op(h)
            const float w = geno[ed.layer * 5 + op];
            const float* bp = bsv + (size_t)ed.layer * (5 * DDIM) + (size_t)op * DDIM + bn + tn;
            float bb[8];
            *(float4*)&bb[0] = *(const float4*)bp;
            *(float4*)&bb[4] = *(const float4*)(bp + 4);

            #pragma unroll
            for (int i = 0; i < 8; i++) {
                #pragma unroll
                for (int j = 0; j < 8; j++) {
                    const float h = acc[i][j] + bb[j];
                    float a;
                    if      (op == 0) a = h;
                    else if (op == 1) a = fmaxf(h, 0.0f);
                    else if (op == 2) a = tanhf(h);
                    else if (op == 3) a = 1.0f / (1.0f + expf(-h));
                    else              a = (h > 0.0f) ? h : 0.2f * h;
                    accs[i][j] = fmaf(w, a, accs[i][j]);
                }
            }
        }
    }

    // ---- write node output tile
    #pragma unroll
    for (int i = 0; i < 8; i++) {
        float* o = out + (size_t)(bm + tm + i) * DDIM + bn + tn;
        *(float4*)o       = *(const float4*)&accs[i][0];
        *(float4*)(o + 4) = *(const float4*)&accs[i][4];
    }
}

extern "C" void kernel_launch(void* const* d_in, const int* in_sizes, int n_in,
                              void* d_out, int out_size)
{
    // Identify inputs by element count (robust to any metadata ambiguity).
    const float *s0 = nullptr, *s1 = nullptr, *geno = nullptr;
    const float *Ws = nullptr, *Wb = nullptr, *bsv = nullptr;
    for (int i = 0; i < n_in; i++) {
        const long sz = (long)in_sizes[i];
        const float* p = (const float*)d_in[i];
        if      (sz == (long)BATCH * DDIM)            { if (!s0) s0 = p; else s1 = p; }
        else if (sz == 90L)                            geno = p;
        else if (sz == 14L * 5 * 1024 * 1024)          Ws   = p;
        else if (sz == 4L * 5 * 2048 * 1024)           Wb   = p;
        else if (sz == 18L * 5 * 1024)                 bsv  = p;
    }

    float *n0, *n1, *n2;
    cudaGetSymbolAddress((void**)&n0, g_node0);
    cudaGetSymbolAddress((void**)&n1, g_node1);
    cudaGetSymbolAddress((void**)&n2, g_node2);

    // states index j -> input pointer (j==2 is the cat edge, handled specially)
    const float* states[6] = { s0, s1, nullptr, n0, n1, n2 };
    float* outs[4] = { n0, n1, n2, (float*)d_out };

    dim3 grid(DDIM / BN, BATCH / BM);   // (8, 32) = 256 CTAs
    dim3 block(NTHREADS);

    int si = 0, bi = 0, offset = 0;
    for (int node = 0; node < 4; node++) {
        NodeArgs na;
        na.n_edges = node + 3;
        for (int j = 0; j < node + 3; j++) {
            EdgeDesc& ed = na.e[j];
            ed.layer = offset + j;
            if (j == 2) {
                ed.W = Wb + (size_t)bi * 5 * 2048 * 1024; bi++;
                ed.K = 2048; ed.ksplit = 1024;
                ed.xa = s0; ed.xb = s1;
            } else {
                ed.W = Ws + (size_t)si * 5 * 1024 * 1024; si++;
                ed.K = 1024; ed.ksplit = 1024;
                ed.xa = states[j]; ed.xb = states[j];
            }
        }
        node_kernel<<<grid, block>>>(na, geno, bsv, outs[node]);
        offset += node + 3;
    }
}

// round 2
// speedup vs baseline: 1.0005x; 1.0005x over previous
#include <cuda_runtime.h>
#include <math.h>

// ----------------------------------------------------------------------------
// DARTS-style supernet forward:
//   states = [s0, s1, cat(s0,s1)]
//   node i (i=0..3): s = sum_j mixed(states[j], W_l, b_l, geno_l), l = offset+j
//   mixed(x,W,b,w) = sum_k w[k] * act_k(x @ W[k] + b[k]),  5 ops
// Output = node 3 result  [4096, 1024] fp32.
//
// This round: fused fp32 SGEMM per node. Each CTA computes a 128x128 tile of
// the node output; loops over (edge, op), runs full-K reduction in registers,
// applies bias + activation + genotype weight, accumulates into a second
// register tile. No intermediates in HBM, no atomics. "cat" edge reads s0 for
// k<1024 and s1 for k>=1024 (no concat buffer).
// ----------------------------------------------------------------------------

#define BM 128
#define BN 128
#define BK 16
#define NTHREADS 256

#define BATCH 4096
#define DDIM  1024

struct EdgeDesc {
    const float* xa;    // input for k <  ksplit
    const float* xb;    // input for k >= ksplit
    const float* W;     // [5, K, 1024]
    int K;              // 1024 or 2048
    int ksplit;         // 1024 (cat edge) or == K (normal edge)
    int layer;          // global layer index l (for genotype / bias)
};

struct NodeArgs {
    EdgeDesc e[6];
    int n_edges;
};

// Scratch for node outputs 0..2 (node 3 goes to d_out). Static device arrays
// per harness rules (no cudaMalloc anywhere).
__device__ float g_node0[BATCH * DDIM];
__device__ float g_node1[BATCH * DDIM];
__device__ float g_node2[BATCH * DDIM];

__global__ __launch_bounds__(NTHREADS, 1)
void node_kernel(NodeArgs args,
                 const float* __restrict__ geno,   // [18,5]
                 const float* __restrict__ bsv,    // [18,5,1024]
                 float* __restrict__ out)          // [4096,1024]
{
    __shared__ float As[BK][BM];   // x tile, transposed: As[k][m]
    __shared__ float Bs[BK][BN];   // W tile: Bs[k][n]

    const int bm = blockIdx.y * BM;
    const int bn = blockIdx.x * BN;
    const int tid = (int)threadIdx.x;
    const int tx = tid & 15;        // 16 thread-cols
    const int ty = tid >> 4;        // 16 thread-rows
    const int tm = ty * 8;
    const int tn = tx * 8;

    float accs[8][8];               // mixed-op accumulator (final tile)
    #pragma unroll
    for (int i = 0; i < 8; i++)
        #pragma unroll
        for (int j = 0; j < 8; j++)
            accs[i][j] = 0.0f;

    for (int e = 0; e < args.n_edges; e++) {
        const EdgeDesc ed = args.e[e];
        const int ntiles = ed.K / BK;

        for (int op = 0; op < 5; op++) {            // do NOT unroll: keeps I$ small
            const float* __restrict__ Wop = ed.W + (size_t)op * ed.K * DDIM;

            float acc[8][8];                        // per-(edge,op) GEMM accumulator
            #pragma unroll
            for (int i = 0; i < 8; i++)
                #pragma unroll
                for (int j = 0; j < 8; j++)
                    acc[i][j] = 0.0f;

            for (int kt = 0; kt < ntiles; kt++) {
                const int kg = kt * BK;
                const float* xbase = ed.xa;
                int koff = kg;
                if (kg >= ed.ksplit) { xbase = ed.xb; koff = kg - ed.ksplit; }

                // ---- load A tile: 128 rows x 16 k-cols (2 float4 per thread)
                #pragma unroll
                for (int rpt = 0; rpt < 2; rpt++) {
                    const int f  = tid + rpt * NTHREADS;   // 0..511
                    const int r  = f >> 2;                 // 0..127
                    const int c4 = f & 3;                  // 0..3
                    float4 v = *(const float4*)(xbase + (size_t)(bm + r) * DDIM + koff + c4 * 4);
                    As[c4 * 4 + 0][r] = v.x;
                    As[c4 * 4 + 1][r] = v.y;
                    As[c4 * 4 + 2][r] = v.z;
                    As[c4 * 4 + 3][r] = v.w;
                }
                // ---- load B tile: 16 k-rows x 128 cols (2 float4 per thread)
                #pragma unroll
                for (int rpt = 0; rpt < 2; rpt++) {
                    const int f  = tid + rpt * NTHREADS;   // 0..511
                    const int r  = f >> 5;                 // 0..15
                    const int c4 = f & 31;                 // 0..31
                    float4 v = *(const float4*)(Wop + (size_t)(kg + r) * DDIM + bn + c4 * 4);
                    *(float4*)&Bs[r][c4 * 4] = v;
                }
                __syncthreads();

                #pragma unroll
                for (int kk = 0; kk < BK; kk++) {
                    float a[8], b[8];
                    *(float4*)&a[0] = *(const float4*)&As[kk][tm];
                    *(float4*)&a[4] = *(const float4*)&As[kk][tm + 4];
                    *(float4*)&b[0] = *(const float4*)&Bs[kk][tn];
                    *(float4*)&b[4] = *(const float4*)&Bs[kk][tn + 4];
                    #pragma unroll
                    for (int i = 0; i < 8; i++)
                        #pragma unroll
                        for (int j = 0; j < 8; j++)
                            acc[i][j] = fmaf(a[i], b[j], acc[i][j]);
                }
                __syncthreads();
            }

            // ---- epilogue: h = acc + bias; accs += w * act_op(h)
            const float w = geno[ed.layer * 5 + op];
            const float* bp = bsv + (size_t)ed.layer * (5 * DDIM) + (size_t)op * DDIM + bn + tn;
            float bb[8];
            *(float4*)&bb[0] = *(const float4*)bp;
            *(float4*)&bb[4] = *(const float4*)(bp + 4);

            #pragma unroll
            for (int i = 0; i < 8; i++) {
                #pragma unroll
                for (int j = 0; j < 8; j++) {
                    const float h = acc[i][j] + bb[j];
                    float a;
                    if      (op == 0) a = h;
                    else if (op == 1) a = fmaxf(h, 0.0f);
                    else if (op == 2) a = tanhf(h);
                    else if (op == 3) a = 1.0f / (1.0f + expf(-h));
                    else              a = (h > 0.0f) ? h : 0.2f * h;
                    accs[i][j] = fmaf(w, a, accs[i][j]);
                }
            }
        }
    }

    // ---- write node output tile
    #pragma unroll
    for (int i = 0; i < 8; i++) {
        float* o = out + (size_t)(bm + tm + i) * DDIM + bn + tn;
        *(float4*)o       = *(const float4*)&accs[i][0];
        *(float4*)(o + 4) = *(const float4*)&accs[i][4];
    }
}

extern "C" void kernel_launch(void* const* d_in, const int* in_sizes, int n_in,
                              void* d_out, int out_size)
{
    // Identify inputs by element count (robust to any metadata ambiguity).
    const float *s0 = nullptr, *s1 = nullptr, *geno = nullptr;
    const float *Ws = nullptr, *Wb = nullptr, *bsv = nullptr;
    for (int i = 0; i < n_in; i++) {
        const long sz = (long)in_sizes[i];
        const float* p = (const float*)d_in[i];
        if      (sz == (long)BATCH * DDIM)            { if (!s0) s0 = p; else s1 = p; }
        else if (sz == 90L)                            geno = p;
        else if (sz == 14L * 5 * 1024 * 1024)          Ws   = p;
        else if (sz == 4L * 5 * 2048 * 1024)           Wb   = p;
        else if (sz == 18L * 5 * 1024)                 bsv  = p;
    }

    float *n0, *n1, *n2;
    cudaGetSymbolAddress((void**)&n0, g_node0);
    cudaGetSymbolAddress((void**)&n1, g_node1);
    cudaGetSymbolAddress((void**)&n2, g_node2);

    // states index j -> input pointer (j==2 is the cat edge, handled specially)
    const float* states[6] = { s0, s1, nullptr, n0, n1, n2 };
    float* outs[4] = { n0, n1, n2, (float*)d_out };

    dim3 grid(DDIM / BN, BATCH / BM);   // (8, 32) = 256 CTAs
    dim3 block(NTHREADS);

    int si = 0, bi = 0, offset = 0;
    for (int node = 0; node < 4; node++) {
        NodeArgs na;
        na.n_edges = node + 3;
        for (int j = 0; j < node + 3; j++) {
            EdgeDesc& ed = na.e[j];
            ed.layer = offset + j;
            if (j == 2) {
                ed.W = Wb + (size_t)bi * 5 * 2048 * 1024; bi++;
                ed.K = 2048; ed.ksplit = 1024;
                ed.xa = s0; ed.xb = s1;
            } else {
                ed.W = Ws + (size_t)si * 5 * 1024 * 1024; si++;
                ed.K = 1024; ed.ksplit = 1024;
                ed.xa = states[j]; ed.xb = states[j];
            }
        }
        node_kernel<<<grid, block>>>(na, geno, bsv, outs[node]);
        offset += node + 3;
    }
}